// round 14
// baseline (speedup 1.0000x reference)
#include <cuda_runtime.h>
#include <cuda_fp16.h>
#include <math.h>
#include <stdint.h>

#define EPSQ 1e-8f
#define TAU 2e-3f
#define NEGINF (-__int_as_float(0x7f800000))
#define NBAR(id, n) asm volatile("bar.sync %0, %1;" :: "r"(id), "r"(n) : "memory")

// normalized codebook: fp32 (exact fixup) + fp16 (MMA), row-major [1024][256]
__device__ float g_cbs[1024 * 256];
__device__ __half g_Bh[1024 * 256];

__device__ __forceinline__ uint32_t smem_u32(const void* p) {
    uint32_t a;
    asm("{ .reg .u64 t; cvta.to.shared.u64 t, %1; cvt.u32.u64 %0, t; }" : "=r"(a) : "l"(p));
    return a;
}
__device__ __forceinline__ void cp16(uint32_t smem_dst, const void* gsrc) {
    asm volatile("cp.async.cg.shared.global [%0], [%1], 16;" :: "r"(smem_dst), "l"(gsrc));
}
__device__ __forceinline__ void cp_commit() { asm volatile("cp.async.commit_group;"); }
template <int Np>
__device__ __forceinline__ void cp_wait() { asm volatile("cp.async.wait_group %0;" :: "n"(Np)); }

__device__ __forceinline__ void ldsm4(uint32_t* r, uint32_t addr) {
    asm volatile("ldmatrix.sync.aligned.m8n8.x4.shared.b16 {%0,%1,%2,%3}, [%4];"
                 : "=r"(r[0]), "=r"(r[1]), "=r"(r[2]), "=r"(r[3]) : "r"(addr));
}
__device__ __forceinline__ void mma16816(float* d, const uint32_t* a, const uint32_t* b) {
    asm volatile(
        "mma.sync.aligned.m16n8k16.row.col.f32.f16.f16.f32 "
        "{%0,%1,%2,%3},{%4,%5,%6,%7},{%8,%9},{%0,%1,%2,%3};"
        : "+f"(d[0]), "+f"(d[1]), "+f"(d[2]), "+f"(d[3])
        : "r"(a[0]), "r"(a[1]), "r"(a[2]), "r"(a[3]), "r"(b[0]), "r"(b[1]));
}

// Branchless screening gumbel (validated R10). selp for u->1 hazard, no BSSY.
__device__ __forceinline__ float gumbel_fast(float u) {
    float d = u - 1.0f;
    float t_near = -d * fmaf(fmaf(0.33333334f, d, -0.5f), d, 1.0f);  // -log1p(d)
    float t_far;
    asm("lg2.approx.f32 %0, %1;" : "=f"(t_far) : "f"(u));
    t_far = t_far * (-0.6931472f);
    float t = (u > 0.999f) ? t_near : t_far;
    float g;
    asm("lg2.approx.f32 %0, %1;" : "=f"(g) : "f"(t));
    return g * (-0.6931472f);
}

// ---- prep: normalize rows -> g_cbs (fp32) + g_Bh (fp16) ----
__global__ void prep_codebook(const float* __restrict__ cb, int K) {
    int row = blockIdx.x * 8 + (threadIdx.x >> 5);
    int lane = threadIdx.x & 31;
    if (row >= K) return;
    const float4* src = (const float4*)(cb + (size_t)row * 256);
    float4 a = src[lane * 2], b = src[lane * 2 + 1];
    float ss = a.x*a.x + a.y*a.y + a.z*a.z + a.w*a.w + b.x*b.x + b.y*b.y + b.z*b.z + b.w*b.w;
#pragma unroll
    for (int off = 16; off; off >>= 1) ss += __shfl_xor_sync(0xffffffffu, ss, off);
    float inv = 1.0f / fmaxf(sqrtf(ss), EPSQ);
    float v[8] = {a.x, a.y, a.z, a.w, b.x, b.y, b.z, b.w};
#pragma unroll
    for (int q = 0; q < 8; q++) {
        int k = lane * 8 + q;
        float x = v[q] * inv;
        g_cbs[(size_t)row * 256 + k] = x;
        g_Bh[(size_t)row * 256 + k] = __float2half_rn(x);
    }
}

// Per-group B prefetch: 32 codebook rows (this group's half of a 64-row chunk)
// into a 16KB stage. 256 threads per group, 4 cp16 each.
__device__ __forceinline__ void issue_B_group(uint32_t dst, int chunk, int grp, int tidl) {
#pragma unroll
    for (int i = 0; i < 4; i++) {
        int idx = tidl + i * 256;
        int n = idx >> 5, c16 = idx & 31;              // n: 0..31 local row
        uint32_t off = (uint32_t)(n * 512) + (uint32_t)((c16 * 16) ^ ((n & 7) << 4));
        cp16(dst + off,
             (const char*)g_Bh + ((size_t)(chunk * 64 + grp * 32 + n) * 256 + c16 * 8) * 2);
    }
    cp_commit();
}

// ---- main: M=256 CTA (512 thr), chunk N=64 (16 chunks), warp grid 8(M)x2(N),
// warp tile 32x32. smem: A_h 256x512B = 128KB @0; B 2 groups x 2 stages x 16KB.
// 192KB -> 1 CTA/SM, 16 warps (same occupancy, ~33% fewer LDSM wavefronts).
__global__ void __launch_bounds__(512, 1)
quant_mma(const float* __restrict__ latent, const float* __restrict__ noise,
          const float* __restrict__ cb, const float* __restrict__ tptr,
          float* __restrict__ out, int K) {
    extern __shared__ char dsm[];
    __shared__ float s_scale[256];
    __shared__ float s_bv[512];
    __shared__ float s_sv[512];
    __shared__ int s_bk2[512];
    __shared__ int s_win[256];
    __shared__ int s_nfix;
    __shared__ int s_fixrows[32];
    __shared__ float s_rv[16];
    __shared__ int s_rk[16];

    const int tid = threadIdx.x, lane = tid & 31, wid = tid >> 5;
    const int wm = wid & 7, wn = wid >> 3;
    const int tidl = tid & 255;                  // index within group
    const int rowbase = blockIdx.x * 256;
    const uint32_t smA = smem_u32(dsm);
    const uint32_t smBg = smA + 131072u + (uint32_t)wn * 32768u;  // group's 2x16KB stages

    if (tid == 0) s_nfix = 0;

    // prologue: each group issues its chunks 0,1
    issue_B_group(smBg, 0, wn, tidl);
    issue_B_group(smBg + 16384u, 1, wn, tidl);

    // A prologue: 2 threads per row (256 rows), fp16 convert + swizzled store + norm
    {
        float tv = *tptr;
        int r = tid >> 1, h2 = tid & 1;
        const float4* ar = (const float4*)(latent + (size_t)(rowbase + r) * 256);
        char* pA = dsm + r * 512;
        uint32_t swr = (uint32_t)((r & 7) << 4);
        float ss = 0.0f;
#pragma unroll
        for (int q = 0; q < 32; q++) {
            int d4 = h2 * 32 + q;
            float4 v = ar[d4];
            ss += v.x * v.x + v.y * v.y + v.z * v.z + v.w * v.w;
            __half h0 = __float2half_rn(v.x), h1 = __float2half_rn(v.y);
            __half h2a = __float2half_rn(v.z), h3 = __float2half_rn(v.w);
            uint2 hp;
            hp.x = (uint32_t)__half_as_ushort(h0) | ((uint32_t)__half_as_ushort(h1) << 16);
            hp.y = (uint32_t)__half_as_ushort(h2a) | ((uint32_t)__half_as_ushort(h3) << 16);
            *(uint2*)(pA + ((uint32_t)(d4 * 8) ^ swr)) = hp;
        }
        ss += __shfl_xor_sync(0xffffffffu, ss, 1);
        if (h2 == 0) s_scale[r] = 1.0f / (fmaxf(sqrtf(ss), EPSQ) * tv);
    }
    __syncthreads();   // A + scales visible; afterwards groups run on named barriers

    // fragment address constants (A/B addressing patterns verified R4/R8/R13)
    const int m8 = lane >> 3, rl = lane & 7;
    const uint32_t sw = (uint32_t)(rl << 4);
    const uint32_t aBase0 = smA + (uint32_t)((wm * 32 + 8 * (m8 & 1) + rl) * 512);
    const uint32_t aBase1 = aBase0 + 16 * 512;
    const uint32_t aKoff = (uint32_t)((m8 >> 1) * 16);
    const uint32_t bRowL = (uint32_t)(((m8 >> 1) * 8 + rl) * 512);   // local rows 0..15
    const uint32_t bKoff = (uint32_t)((m8 & 1) * 16);
    const int barid = 1 + wn;

    // epilogue state: 4 owned rows x 32 owned cols (8 per n-tile pair)
    const int eR = wm * 32 + (lane >> 2);
    const float* nrow[4];
    float sc[4], best[4], sec[4];
    int bk[4];
#pragma unroll
    for (int ri = 0; ri < 4; ri++) {
        int R = eR + (ri & 1) * 8 + (ri >> 1) * 16;
        nrow[ri] = noise + (size_t)(rowbase + R) * K;
        sc[ri] = s_scale[R];
        best[ri] = NEGINF; sec[ri] = NEGINF; bk[ri] = 0;
    }

    const int NCH = K >> 6;  // 16
    for (int c = 0; c < NCH; c++) {
        int cb0 = c * 64 + wn * 32 + (lane & 3) * 2;
        // noise prefetch, rows 0-1 only (register pressure: rows 2-3 after mainloop)
        float2 u01[2][4];
#pragma unroll
        for (int ri = 0; ri < 2; ri++)
#pragma unroll
            for (int q = 0; q < 4; q++) u01[ri][q] = *(const float2*)(nrow[ri] + cb0 + q * 8);
        if (c < NCH - 1) cp_wait<1>(); else cp_wait<0>();
        NBAR(barid, 256);           // group: stage for chunk c ready

        const uint32_t Bst = smBg + (uint32_t)((c & 1) * 16384);
        float acc[2][4][4];
#pragma unroll
        for (int i = 0; i < 2; i++)
#pragma unroll
            for (int j = 0; j < 4; j++)
#pragma unroll
                for (int q = 0; q < 4; q++) acc[i][j][q] = 0.0f;

#pragma unroll
        for (int ks = 0; ks < 16; ks++) {
            uint32_t offA = ((uint32_t)(ks * 32) + aKoff) ^ sw;
            uint32_t offB = ((uint32_t)(ks * 32) + bKoff) ^ sw;
            uint32_t b0[4], b1[4], a0[4], a1[4];
            ldsm4(b0, Bst + bRowL + offB);            // local rows 0-15  -> n-tiles 0,1
            ldsm4(b1, Bst + 8192u + bRowL + offB);    // local rows 16-31 -> n-tiles 2,3
            ldsm4(a0, aBase0 + offA);
            ldsm4(a1, aBase1 + offA);
            mma16816(acc[0][0], a0, b0);
            mma16816(acc[0][1], a0, b0 + 2);
            mma16816(acc[0][2], a0, b1);
            mma16816(acc[0][3], a0, b1 + 2);
            mma16816(acc[1][0], a1, b0);
            mma16816(acc[1][1], a1, b0 + 2);
            mma16816(acc[1][2], a1, b1);
            mma16816(acc[1][3], a1, b1 + 2);
        }
        NBAR(barid, 256);           // group done reading stage (fence cp.async off LDSM)

        // prefetch c+2 into the stage just read (group-local)
        if (c + 2 < NCH) issue_B_group(smBg + (uint32_t)((c & 1) * 16384), c + 2, wn, tidl);

        // noise rows 2-3 (overlaps epilogue of rows 0-1)
        float2 u23[2][4];
#pragma unroll
        for (int ri = 0; ri < 2; ri++)
#pragma unroll
            for (int q = 0; q < 4; q++) u23[ri][q] = *(const float2*)(nrow[2 + ri] + cb0 + q * 8);

        // epilogue: scale + fast gumbel + running top-2 (ri = mt*2+hi)
#pragma unroll
        for (int ri = 0; ri < 4; ri++) {
            int mt = ri >> 1, hi = ri & 1;
            float b0v = best[ri], s0 = sec[ri];
            int k0 = bk[ri];
#pragma unroll
            for (int nt = 0; nt < 4; nt++) {
                float2 uu = (ri < 2) ? u01[ri][nt] : u23[ri - 2][nt];
                float g0 = gumbel_fast(uu.x);
                float g1 = gumbel_fast(uu.y);
                float l0 = fmaf(acc[mt][nt][hi * 2 + 0], sc[ri], g0);
                float l1 = fmaf(acc[mt][nt][hi * 2 + 1], sc[ri], g1);
                int kk = cb0 + nt * 8;
                if (l0 > b0v) { s0 = b0v; b0v = l0; k0 = kk; } else if (l0 > s0) s0 = l0;
                if (l1 > b0v) { s0 = b0v; b0v = l1; k0 = kk + 1; } else if (l1 > s0) s0 = l1;
            }
            best[ri] = b0v; sec[ri] = s0; bk[ri] = k0;
        }
    }

    // quad reduce: union top-2 (strict >, ties -> smaller k)
#pragma unroll
    for (int ri = 0; ri < 4; ri++) {
        float v = best[ri], s2 = sec[ri];
        int k = bk[ri];
#pragma unroll
        for (int off = 1; off <= 2; off <<= 1) {
            float ov = __shfl_xor_sync(0xffffffffu, v, off);
            float os = __shfl_xor_sync(0xffffffffu, s2, off);
            int ok = __shfl_xor_sync(0xffffffffu, k, off);
            float nb = fmaxf(v, ov);
            float ns = fmaxf(fminf(v, ov), fmaxf(s2, os));
            k = (ov > v || (ov == v && ok < k)) ? ok : k;
            v = nb; s2 = ns;
        }
        if ((lane & 3) == 0) {
            int R = eR + (ri & 1) * 8 + (ri >> 1) * 16;
            s_bv[R * 2 + wn] = v;
            s_sv[R * 2 + wn] = s2;
            s_bk2[R * 2 + wn] = k;
        }
    }
    __syncthreads();
    if (tid < 256) {
        float v0 = s_bv[tid * 2], v1 = s_bv[tid * 2 + 1];
        float q0 = s_sv[tid * 2], q1 = s_sv[tid * 2 + 1];
        int k0 = s_bk2[tid * 2], k1 = s_bk2[tid * 2 + 1];
        float vb = fmaxf(v0, v1);
        float vs = fmaxf(fminf(v0, v1), fmaxf(q0, q1));
        s_win[tid] = (v1 > v0 || (v1 == v0 && k1 < k0)) ? k1 : k0;
        if (vb - vs < TAU) {
            int i = atomicAdd(&s_nfix, 1);
            if (i < 32) s_fixrows[i] = tid;
        }
    }
    __syncthreads();

    // exact fp32 fixup for flagged rows (expected ~0.5 per CTA; accurate logf)
    int nf = s_nfix < 32 ? s_nfix : 32;
    for (int f = 0; f < nf; f++) {
        int r = s_fixrows[f];
        const float4* a4 = (const float4*)(latent + (size_t)(rowbase + r) * 256);
        const float* nz = noise + (size_t)(rowbase + r) * K;
        float scr = s_scale[r];
        float bv = NEGINF;
        int bki = 0;
        for (int k = tid; k < K; k += 512) {
            const float4* b4 = (const float4*)(g_cbs + (size_t)k * 256);
            float dot = 0.0f;
#pragma unroll 8
            for (int d4 = 0; d4 < 64; d4++) {
                float4 av = a4[d4], bb = b4[d4];
                dot = fmaf(av.x, bb.x, dot);
                dot = fmaf(av.y, bb.y, dot);
                dot = fmaf(av.z, bb.z, dot);
                dot = fmaf(av.w, bb.w, dot);
            }
            float lg = fmaf(dot, scr, -logf(-logf(nz[k])));
            if (lg > bv) { bv = lg; bki = k; }
        }
#pragma unroll
        for (int off = 16; off >= 1; off >>= 1) {
            float ov = __shfl_xor_sync(0xffffffffu, bv, off);
            int ok = __shfl_xor_sync(0xffffffffu, bki, off);
            if (ov > bv || (ov == bv && ok < bki)) { bv = ov; bki = ok; }
        }
        if (lane == 0) { s_rv[wid] = bv; s_rk[wid] = bki; }
        __syncthreads();
        if (tid == 0) {
            float v = s_rv[0]; int kk = s_rk[0];
#pragma unroll
            for (int w = 1; w < 16; w++)
                if (s_rv[w] > v || (s_rv[w] == v && s_rk[w] < kk)) { v = s_rv[w]; kk = s_rk[w]; }
            s_win[r] = kk;
        }
        __syncthreads();
    }

    // gather winning codebook rows (original fp32 codebook)
    const float4* cb4 = (const float4*)cb;
    float4* o4 = (float4*)out;
#pragma unroll
    for (int t = 0; t < 32; t++) {
        int idx = tid + t * 512;
        int r = idx >> 6, d4 = idx & 63;
        o4[(size_t)(rowbase + r) * 64 + d4] = cb4[(size_t)s_win[r] * 64 + d4];
    }
}

extern "C" void kernel_launch(void* const* d_in, const int* in_sizes, int n_in,
                              void* d_out, int out_size) {
    const float* latent = (const float*)d_in[0];
    const float* noise  = (const float*)d_in[1];
    const float* cb     = (const float*)d_in[2];
    const float* tptr   = (const float*)d_in[3];

    double s0 = (double)in_sizes[0], s1 = (double)in_sizes[1], s2 = (double)in_sizes[2];
    int D = (int)llround(sqrt(s0 * s2 / s1));   // 256
    int K = in_sizes[2] / D;                    // 1024
    int N = in_sizes[0] / D;                    // 131072

    prep_codebook<<<K / 8, 256>>>(cb, K);

    int shm = 196608;  // 192 KB dynamic (A 128K + B 64K) -> 1 CTA/SM, 16 warps
    cudaFuncSetAttribute(quant_mma, cudaFuncAttributeMaxDynamicSharedMemorySize, shm);
    quant_mma<<<N / 256, 512, shm>>>(latent, noise, cb, tptr, (float*)d_out, K);
}

// round 15
// speedup vs baseline: 1.6505x; 1.6505x over previous
#include <cuda_runtime.h>
#include <math.h>
#include <stdint.h>

#define EPSQ 1e-8f
#define NEGINF (-__int_as_float(0x7f800000))

// row-normalized codebook, fp32 [1024][256]
__device__ float g_cbs[1024 * 256];

// ---- prep: normalize codebook rows -> g_cbs ----
__global__ void prep_codebook(const float* __restrict__ cb, int K) {
    int row = blockIdx.x * 8 + (threadIdx.x >> 5);
    int lane = threadIdx.x & 31;
    if (row >= K) return;
    const float4* src = (const float4*)(cb + (size_t)row * 256);
    float4 a = src[lane * 2], b = src[lane * 2 + 1];
    float ss = a.x*a.x + a.y*a.y + a.z*a.z + a.w*a.w + b.x*b.x + b.y*b.y + b.z*b.z + b.w*b.w;
#pragma unroll
    for (int off = 16; off; off >>= 1) ss += __shfl_xor_sync(0xffffffffu, ss, off);
    float inv = 1.0f / fmaxf(sqrtf(ss), EPSQ);
    float4* dst = (float4*)(g_cbs + (size_t)row * 256);
    a.x *= inv; a.y *= inv; a.z *= inv; a.w *= inv;
    b.x *= inv; b.y *= inv; b.z *= inv; b.w *= inv;
    dst[lane * 2] = a;
    dst[lane * 2 + 1] = b;
}

// ---- main: one warp per row. Gumbel-dominance screening, exact fp32 verify. ----
// Bound: |cos/temp| <= 1/temp exactly (codebook normalized, Cauchy-Schwarz), so the
// argmax row winner must have gumbel >= gmax - 2/temp. Gumbel is monotone in u, so
// candidates = { k : u_k >= uthr } with uthr = G^{-1}(gmax - margin), expected
// e^margin ~ 7.6 per row. Only candidates get the exact fp32 dot + accurate logf
// chain (identical arithmetic to the fixup path that has measured rel_err 0.0).
__global__ void __launch_bounds__(256)
quant_screen(const float* __restrict__ latent, const float* __restrict__ noise,
             const float* __restrict__ cb, const float* __restrict__ tptr,
             float* __restrict__ out, int K) {
    const int lane = threadIdx.x & 31;
    const int warp = threadIdx.x >> 5;
    const size_t row = (size_t)blockIdx.x * 8 + warp;

    // 1) stream the noise row into registers, running per-lane max
    const float4* u4 = (const float4*)(noise + row * (size_t)K);
    float4 v[8];
    float m = 0.0f;
#pragma unroll
    for (int j = 0; j < 8; j++) {
        v[j] = u4[j * 32 + lane];
        m = fmaxf(m, fmaxf(fmaxf(v[j].x, v[j].y), fmaxf(v[j].z, v[j].w)));
    }
#pragma unroll
    for (int off = 16; off; off >>= 1) m = fmaxf(m, __shfl_xor_sync(0xffffffffu, m, off));
    // m = umax (uniform across warp)

    // 2) latent row + norm
    const float4* l4 = (const float4*)(latent + row * 256);
    float4 a0 = l4[lane], a1 = l4[32 + lane];
    float ss = a0.x*a0.x + a0.y*a0.y + a0.z*a0.z + a0.w*a0.w
             + a1.x*a1.x + a1.y*a1.y + a1.z*a1.z + a1.w*a1.w;
#pragma unroll
    for (int off = 16; off; off >>= 1) ss += __shfl_xor_sync(0xffffffffu, ss, off);
    float temp = *tptr;
    float sc = 1.0f / (fmaxf(sqrtf(ss), EPSQ) * temp);

    // 3) threshold, computed in w = 1-u space (fp32-robust for umax near 1):
    //    -ln(umax) via log1pf; uthr s.t. -ln(uthr) = e^margin * (-ln(umax)).
    //    margin pads the rigorous 2/temp bound by 0.03 g-units (>> transform error).
    float wmax = 1.0f - m;                       // exact (Sterbenz) for m >= 0.5
    float nlu = -log1pf(-wmax);                  // -ln(umax), accurate near 1
    float margin = (2.0f / temp) * 1.0001f + 0.03f;
    float em = expf(margin);
    float wthr = -expm1f(-em * nlu);             // 1 - uthr, accurate
    float uthr = fminf(1.0f - wthr, m);          // clamp: umax always a candidate

    // 4) scan slots; for each candidate, warp-cooperative exact fp32 logit
    float best = NEGINF;
    int bkk = 0x7fffffff;
#pragma unroll
    for (int j = 0; j < 8; j++) {
        float uu[4] = {v[j].x, v[j].y, v[j].z, v[j].w};
#pragma unroll
        for (int t = 0; t < 4; t++) {
            unsigned mask = __ballot_sync(0xffffffffu, uu[t] >= uthr);
            while (mask) {
                int L = __ffs(mask) - 1;
                mask &= mask - 1;
                float uv = __shfl_sync(0xffffffffu, uu[t], L);
                int k = j * 128 + L * 4 + t;
                const float4* b4 = (const float4*)(g_cbs + (size_t)k * 256);
                float4 b0 = b4[lane], b1 = b4[32 + lane];
                float d = a0.x*b0.x + a0.y*b0.y + a0.z*b0.z + a0.w*b0.w
                        + a1.x*b1.x + a1.y*b1.y + a1.z*b1.z + a1.w*b1.w;
#pragma unroll
                for (int off = 16; off; off >>= 1) d += __shfl_xor_sync(0xffffffffu, d, off);
                float g = -logf(-logf(uv));      // accurate chain (reference semantics)
                float lg = fmaf(d, sc, g);
                if (lg > best || (lg == best && k < bkk)) { best = lg; bkk = k; }
            }
        }
    }

    // 5) gather winner row from ORIGINAL codebook
    const float4* c4 = (const float4*)(cb + (size_t)bkk * 256);
    float4* o4 = (float4*)(out + row * 256);
    o4[lane] = c4[lane];
    o4[32 + lane] = c4[32 + lane];
}

extern "C" void kernel_launch(void* const* d_in, const int* in_sizes, int n_in,
                              void* d_out, int out_size) {
    const float* latent = (const float*)d_in[0];
    const float* noise  = (const float*)d_in[1];
    const float* cb     = (const float*)d_in[2];
    const float* tptr   = (const float*)d_in[3];

    double s0 = (double)in_sizes[0], s1 = (double)in_sizes[1], s2 = (double)in_sizes[2];
    int D = (int)llround(sqrt(s0 * s2 / s1));   // 256
    int K = in_sizes[2] / D;                    // 1024
    int N = in_sizes[0] / D;                    // 131072

    prep_codebook<<<K / 8, 256>>>(cb, K);
    quant_screen<<<N / 8, 256>>>(latent, noise, cb, tptr, (float*)d_out, K);
}